// round 15
// baseline (speedup 1.0000x reference)
#include <cuda_runtime.h>
#include <math.h>

// Problem constants (fixed by the dataset)
#define NN     50000
#define EE     800000
#define F_IN   16
#define EMB    32
#define HH     4
#define HCC    128   // EMB*H
#define LL     2
#define DENSE  128

// ---------------------------------------------------------------------------
// Scratch (static device globals — no runtime allocation allowed)
// ---------------------------------------------------------------------------
__device__ __align__(16) float g_q[(size_t)NN * HCC];
__device__ __align__(16) float g_k[(size_t)NN * HCC];
__device__ __align__(16) float g_v[(size_t)NN * HCC];
__device__ __align__(16) float g_o[(size_t)NN * HCC];   // skip + aggregated msgs
__device__ __align__(16) float g_h[(size_t)NN * EMB];   // node features between layers
__device__ __align__(16) float g_p[(size_t)EE * HH];    // logits, then exp(logits-m)
__device__ __align__(16) float g_m[(size_t)NN * HH];    // segment max
__device__ __align__(16) float g_z[(size_t)NN * HH];    // segment sum

// ---------------------------------------------------------------------------
// Generic tiled linear: Y[n,OUT] = act(X[n,F] @ W[F,OUT] + B)
// 128 threads/block, 32 nodes/block. Thread owns one output column and
// accumulates 8 nodes in registers -> each W load feeds 8 FMAs (FFMA-bound).
// ---------------------------------------------------------------------------
template <int F, int OUT, bool RELU>
__global__ void linear_kernel(const float* __restrict__ X,
                              const float* __restrict__ W,
                              const float* __restrict__ B,
                              float* __restrict__ Y, int n)
{
    constexpr int SUBS = 128 / OUT;     // column groups per block
    constexpr int NPS  = 32 / SUBS;     // nodes per column-group
    constexpr int NCH  = NPS / 8;       // chunks of 8 nodes

    __shared__ float sh[32 * F];

    const int tid  = threadIdx.x;
    const int col  = tid % OUT;
    const int sub  = tid / OUT;
    const int base = blockIdx.x * 32;

    // load X tile (coalesced; zero-pad past n)
    for (int i = tid; i < 32 * F; i += 128) {
        int node = base + i / F;
        sh[i] = (node < n) ? X[(size_t)base * F + i] : 0.f;
    }
    __syncthreads();

    const float bcol = B[col];
    const int nb = sub * NPS;

    for (int c = 0; c < NCH; ++c) {
        float acc[8];
#pragma unroll
        for (int j = 0; j < 8; ++j) acc[j] = bcol;

#pragma unroll 8
        for (int d = 0; d < F; ++d) {
            float w = W[d * OUT + col];
            const float* hrow = &sh[(nb + c * 8) * F + d];
#pragma unroll
            for (int j = 0; j < 8; ++j)
                acc[j] += hrow[j * F] * w;
        }

#pragma unroll
        for (int j = 0; j < 8; ++j) {
            int node = base + nb + c * 8 + j;
            if (node < n) {
                float vv = acc[j];
                if (RELU) vv = fmaxf(vv, 0.f);
                Y[(size_t)node * OUT + col] = vv;
            }
        }
    }
}

// ---------------------------------------------------------------------------
// Segment-softmax helpers
// ---------------------------------------------------------------------------
__global__ void init_mz_kernel(float* __restrict__ m, float* __restrict__ z, int n4)
{
    int i = blockIdx.x * blockDim.x + threadIdx.x;
    if (i < n4) { m[i] = -3.0e38f; z[i] = 0.f; }
}

__device__ __forceinline__ void atomicMaxF(float* addr, float val)
{
    int* ia = (int*)addr;
    int old = __float_as_int(*addr);
    while (__int_as_float(old) < val) {
        int assumed = old;
        old = atomicCAS(ia, assumed, __float_as_int(val));
        if (old == assumed) break;
    }
}

// Pass A: one warp per edge. lane = h*8+g, g covers 4 channels (float4).
// logits[e,h] = dot(q[dst,h,:], k[src,h,:] + edge_bias[h,:]) / sqrt(EMB)
__global__ void edge_logits_kernel(const float* __restrict__ q,
                                   const float* __restrict__ k,
                                   const int*   __restrict__ ei,
                                   const float* __restrict__ ea,
                                   const float* __restrict__ We,
                                   float* __restrict__ logits,
                                   float* __restrict__ m, int E_)
{
    int gt = blockIdx.x * blockDim.x + threadIdx.x;
    int e  = gt >> 5;
    if (e >= E_) return;
    int lane = threadIdx.x & 31;
    int h = lane >> 3, g = lane & 7;
    int off = h * 32 + g * 4;

    int src = ei[e];
    int dst = ei[E_ + e];

    float4 q4 = *(const float4*)(q + (size_t)dst * HCC + off);
    float4 k4 = *(const float4*)(k + (size_t)src * HCC + off);

    float a0 = ea[e * 4 + 0], a1 = ea[e * 4 + 1];
    float a2 = ea[e * 4 + 2], a3 = ea[e * 4 + 3];
    float4 w0 = *(const float4*)(We + 0 * HCC + off);
    float4 w1 = *(const float4*)(We + 1 * HCC + off);
    float4 w2 = *(const float4*)(We + 2 * HCC + off);
    float4 w3 = *(const float4*)(We + 3 * HCC + off);

    float ebx = a0 * w0.x + a1 * w1.x + a2 * w2.x + a3 * w3.x;
    float eby = a0 * w0.y + a1 * w1.y + a2 * w2.y + a3 * w3.y;
    float ebz = a0 * w0.z + a1 * w1.z + a2 * w2.z + a3 * w3.z;
    float ebw = a0 * w0.w + a1 * w1.w + a2 * w2.w + a3 * w3.w;

    float s = q4.x * (k4.x + ebx) + q4.y * (k4.y + eby)
            + q4.z * (k4.z + ebz) + q4.w * (k4.w + ebw);

    s += __shfl_xor_sync(0xFFFFFFFFu, s, 4);
    s += __shfl_xor_sync(0xFFFFFFFFu, s, 2);
    s += __shfl_xor_sync(0xFFFFFFFFu, s, 1);

    if (g == 0) {
        float lg = s * 0.17677669529663687f;   // 1/sqrt(32)
        logits[(size_t)e * HH + h] = lg;
        atomicMaxF(&m[dst * HH + h], lg);
    }
}

// Pass B: one thread per (edge, head): p = exp(l - m[dst]); z[dst] += p
__global__ void edge_p_kernel(float* __restrict__ logits,
                              const int*   __restrict__ ei,
                              const float* __restrict__ m,
                              float* __restrict__ z, int E_)
{
    int i = blockIdx.x * blockDim.x + threadIdx.x;
    if (i >= E_ * HH) return;
    int e = i >> 2, h = i & 3;
    int dst = ei[E_ + e];
    float p = __expf(logits[i] - m[dst * HH + h]);
    logits[i] = p;
    atomicAdd(&z[dst * HH + h], p);
}

// Pass C: one thread per (edge, head, channel-quad); vector red to out[dst].
__global__ void edge_msg_kernel(const float* __restrict__ v,
                                const int*   __restrict__ ei,
                                const float* __restrict__ ea,
                                const float* __restrict__ We,
                                const float* __restrict__ p,
                                const float* __restrict__ z,
                                float* __restrict__ out, int E_)
{
    int i = blockIdx.x * blockDim.x + threadIdx.x;
    if (i >= E_ * 32) return;
    int e = i >> 5;
    int r = i & 31;
    int h = r >> 3, g = r & 7;
    int off = h * 32 + g * 4;

    int src = ei[e];
    int dst = ei[E_ + e];

    float alpha = p[(size_t)e * HH + h] / (z[dst * HH + h] + 1e-16f);

    float4 v4 = *(const float4*)(v + (size_t)src * HCC + off);

    float a0 = ea[e * 4 + 0], a1 = ea[e * 4 + 1];
    float a2 = ea[e * 4 + 2], a3 = ea[e * 4 + 3];
    float4 w0 = *(const float4*)(We + 0 * HCC + off);
    float4 w1 = *(const float4*)(We + 1 * HCC + off);
    float4 w2 = *(const float4*)(We + 2 * HCC + off);
    float4 w3 = *(const float4*)(We + 3 * HCC + off);

    float rx = (v4.x + a0 * w0.x + a1 * w1.x + a2 * w2.x + a3 * w3.x) * alpha;
    float ry = (v4.y + a0 * w0.y + a1 * w1.y + a2 * w2.y + a3 * w3.y) * alpha;
    float rz = (v4.z + a0 * w0.z + a1 * w1.z + a2 * w2.z + a3 * w3.z) * alpha;
    float rw = (v4.w + a0 * w0.w + a1 * w1.w + a2 * w2.w + a3 * w3.w) * alpha;

    float* dp = out + (size_t)dst * HCC + off;
    asm volatile("red.global.add.v4.f32 [%0], {%1,%2,%3,%4};"
                 :: "l"(dp), "f"(rx), "f"(ry), "f"(rz), "f"(rw) : "memory");
}

// ---------------------------------------------------------------------------
// Dense head final layer: warp per node, dot(t2[node,0:64], W3) -> sigmoid
// ---------------------------------------------------------------------------
__global__ void dense3_kernel(const float* __restrict__ t2,
                              const float* __restrict__ W3,
                              const float* __restrict__ b3,
                              float* __restrict__ out, int n)
{
    int w = (blockIdx.x * blockDim.x + threadIdx.x) >> 5;
    int lane = threadIdx.x & 31;
    if (w >= n) return;
    float s = t2[(size_t)w * 64 + lane]      * W3[lane]
            + t2[(size_t)w * 64 + 32 + lane] * W3[32 + lane];
#pragma unroll
    for (int o = 16; o; o >>= 1) s += __shfl_xor_sync(0xFFFFFFFFu, s, o);
    if (lane == 0) out[w] = 1.f / (1.f + expf(-(s + b3[0])));
}

// ---------------------------------------------------------------------------
// Launch: 3 x (4 projections, softmax 3-pass, transform) + dense head
// ---------------------------------------------------------------------------
extern "C" void kernel_launch(void* const* d_in, const int* in_sizes, int n_in,
                              void* d_out, int out_size)
{
    const float* x   = (const float*)d_in[0];
    const int*   ei  = (const int*)  d_in[1];
    const float* ea  = (const float*)d_in[2];
    const float* Wq0 = (const float*)d_in[3];  const float* bq0 = (const float*)d_in[4];
    const float* Wk0 = (const float*)d_in[5];  const float* bk0 = (const float*)d_in[6];
    const float* Wv0 = (const float*)d_in[7];  const float* bv0 = (const float*)d_in[8];
    const float* We0 = (const float*)d_in[9];
    const float* Ws0 = (const float*)d_in[10]; const float* bs0 = (const float*)d_in[11];
    const float* Wt0 = (const float*)d_in[12]; const float* bt0 = (const float*)d_in[13];
    const float* Wq  = (const float*)d_in[14]; const float* bq  = (const float*)d_in[15];
    const float* Wk  = (const float*)d_in[16]; const float* bk  = (const float*)d_in[17];
    const float* Wv  = (const float*)d_in[18]; const float* bv  = (const float*)d_in[19];
    const float* We  = (const float*)d_in[20];
    const float* Ws  = (const float*)d_in[21]; const float* bs  = (const float*)d_in[22];
    const float* Wt  = (const float*)d_in[23]; const float* bt  = (const float*)d_in[24];
    const float* W1  = (const float*)d_in[25]; const float* b1  = (const float*)d_in[26];
    const float* W2  = (const float*)d_in[27]; const float* b2  = (const float*)d_in[28];
    const float* W3  = (const float*)d_in[29]; const float* b3  = (const float*)d_in[30];

    const int n  = in_sizes[0] / F_IN;
    const int E_ = in_sizes[1] / 2;

    float *q, *k, *v, *o, *h, *p, *m, *z;
    cudaGetSymbolAddress((void**)&q, g_q);
    cudaGetSymbolAddress((void**)&k, g_k);
    cudaGetSymbolAddress((void**)&v, g_v);
    cudaGetSymbolAddress((void**)&o, g_o);
    cudaGetSymbolAddress((void**)&h, g_h);
    cudaGetSymbolAddress((void**)&p, g_p);
    cudaGetSymbolAddress((void**)&m, g_m);
    cudaGetSymbolAddress((void**)&z, g_z);

    const int LBLK = (n + 31) / 32;
    const int GB_E32 = (E_ * 32 + 255) / 256;   // warp-per-edge / quad kernels
    const int GB_E4  = (E_ * HH + 255) / 256;
    const int GB_MZ  = (n * HH + 255) / 256;

    float* out = (float*)d_out;

    // ---- layer 0 (F_IN=16 -> HC=128) ----
    linear_kernel<F_IN, HCC, false><<<LBLK, 128>>>(x, Wq0, bq0, q, n);
    linear_kernel<F_IN, HCC, false><<<LBLK, 128>>>(x, Wk0, bk0, k, n);
    linear_kernel<F_IN, HCC, false><<<LBLK, 128>>>(x, Wv0, bv0, v, n);
    linear_kernel<F_IN, HCC, false><<<LBLK, 128>>>(x, Ws0, bs0, o, n);
    init_mz_kernel<<<GB_MZ, 256>>>(m, z, n * HH);
    edge_logits_kernel<<<GB_E32, 256>>>(q, k, ei, ea, We0, p, m, E_);
    edge_p_kernel<<<GB_E4, 256>>>(p, ei, m, z, E_);
    edge_msg_kernel<<<GB_E32, 256>>>(v, ei, ea, We0, p, z, o, E_);
    linear_kernel<HCC, EMB, true><<<LBLK, 128>>>(o, Wt0, bt0, h, n);

    // ---- inner layers (EMB=32 -> HC=128) ----
    for (int i = 0; i < LL; ++i) {
        const float* Wqi = Wq + (size_t)i * EMB * HCC;
        const float* Wki = Wk + (size_t)i * EMB * HCC;
        const float* Wvi = Wv + (size_t)i * EMB * HCC;
        const float* Wsi = Ws + (size_t)i * EMB * HCC;
        const float* Wei = We + (size_t)i * 4 * HCC;
        const float* Wti = Wt + (size_t)i * HCC * EMB;
        const float* bqi = bq + (size_t)i * HCC;
        const float* bki = bk + (size_t)i * HCC;
        const float* bvi = bv + (size_t)i * HCC;
        const float* bsi = bs + (size_t)i * HCC;
        const float* bti = bt + (size_t)i * EMB;

        linear_kernel<EMB, HCC, false><<<LBLK, 128>>>(h, Wqi, bqi, q, n);
        linear_kernel<EMB, HCC, false><<<LBLK, 128>>>(h, Wki, bki, k, n);
        linear_kernel<EMB, HCC, false><<<LBLK, 128>>>(h, Wvi, bvi, v, n);
        linear_kernel<EMB, HCC, false><<<LBLK, 128>>>(h, Wsi, bsi, o, n);
        init_mz_kernel<<<GB_MZ, 256>>>(m, z, n * HH);
        edge_logits_kernel<<<GB_E32, 256>>>(q, k, ei, ea, Wei, p, m, E_);
        edge_p_kernel<<<GB_E4, 256>>>(p, ei, m, z, E_);
        edge_msg_kernel<<<GB_E32, 256>>>(v, ei, ea, Wei, p, z, o, E_);
        linear_kernel<HCC, EMB, true><<<LBLK, 128>>>(o, Wti, bti, h, n);
    }

    // ---- dense head: 32->128 relu, 128->64 relu, 64->1 sigmoid ----
    linear_kernel<EMB, DENSE, true><<<LBLK, 128>>>(h, W1, b1, q, n);        // t1 in g_q
    linear_kernel<DENSE, DENSE / 2, true><<<LBLK, 128>>>(q, W2, b2, k, n);  // t2 in g_k
    dense3_kernel<<<(n * 32 + 255) / 256, 256>>>(k, W3, b3, out, n);
}

// round 16
// speedup vs baseline: 1.9634x; 1.9634x over previous
#include <cuda_runtime.h>
#include <math.h>

// Problem constants (fixed by the dataset)
#define NN     50000
#define EE     800000
#define F_IN   16
#define EMB    32
#define HH     4
#define HCC    128   // EMB*H
#define LL     2
#define DENSE  128

// ---------------------------------------------------------------------------
// Scratch (static device globals — no runtime allocation allowed)
// ---------------------------------------------------------------------------
__device__ __align__(16) float g_k[(size_t)NN * HCC];
__device__ __align__(16) float g_v[(size_t)NN * HCC];
__device__ __align__(16) float g_h[(size_t)NN * EMB];
__device__ __align__(16) float g_h2[(size_t)NN * EMB];
__device__ __align__(16) float g_t1[(size_t)NN * DENSE];
__device__ __align__(16) float g_t2[(size_t)NN * (DENSE / 2)];
// CSR (built once per launch, reused by all 3 layers)
__device__ int g_deg[NN];
__device__ int g_start[NN + 1];
__device__ int g_cur[NN];
__device__ int g_csr_src[EE];
__device__ __align__(16) float g_csr_ea[(size_t)EE * 4];
__device__ int g_bsum[64];

// ---------------------------------------------------------------------------
// CSR build kernels
// ---------------------------------------------------------------------------
__global__ void zero_deg_kernel(int* __restrict__ deg, int n)
{
    int i = blockIdx.x * blockDim.x + threadIdx.x;
    if (i < n) deg[i] = 0;
}

__global__ void hist_kernel(const int* __restrict__ ei, int* __restrict__ deg, int E_)
{
    int e = blockIdx.x * blockDim.x + threadIdx.x;
    if (e < E_) atomicAdd(&deg[ei[E_ + e]], 1);
}

// per-block inclusive scan (Hillis-Steele), partial results to start[i+1]
__global__ void scan1_kernel(const int* __restrict__ deg, int* __restrict__ start,
                             int* __restrict__ bsum, int n)
{
    __shared__ int sh[1024];
    int i = blockIdx.x * 1024 + threadIdx.x;
    int v = (i < n) ? deg[i] : 0;
    sh[threadIdx.x] = v;
    __syncthreads();
    for (int off = 1; off < 1024; off <<= 1) {
        int t = (threadIdx.x >= off) ? sh[threadIdx.x - off] : 0;
        __syncthreads();
        sh[threadIdx.x] += t;
        __syncthreads();
    }
    if (i < n) start[i + 1] = sh[threadIdx.x];
    if (threadIdx.x == 1023) bsum[blockIdx.x] = sh[1023];
}

__global__ void scan2_kernel(int* __restrict__ bsum, int nb)
{
    if (threadIdx.x == 0 && blockIdx.x == 0) {
        int acc = 0;
        for (int b = 0; b < nb; ++b) { int t = bsum[b]; bsum[b] = acc; acc += t; }
    }
}

__global__ void scan3_kernel(int* __restrict__ start, int* __restrict__ cur,
                             const int* __restrict__ deg, const int* __restrict__ bsum, int n)
{
    int i = blockIdx.x * blockDim.x + threadIdx.x;
    if (i >= n) return;
    int incl = start[i + 1] + bsum[i >> 10];
    start[i + 1] = incl;
    cur[i] = incl - deg[i];
    if (i == 0) start[0] = 0;
}

__global__ void scatter_kernel(const int* __restrict__ ei, const float* __restrict__ ea,
                               int* __restrict__ cur, int* __restrict__ csr_src,
                               float* __restrict__ csr_ea, int E_)
{
    int e = blockIdx.x * blockDim.x + threadIdx.x;
    if (e >= E_) return;
    int dst = ei[E_ + e];
    int pos = atomicAdd(&cur[dst], 1);
    csr_src[pos] = ei[e];
    *(float4*)(csr_ea + (size_t)pos * 4) = *(const float4*)(ea + (size_t)e * 4);
}

// ---------------------------------------------------------------------------
// Fused k/v projection: one X tile feeds both weight matrices.
// 128 threads/block (one per output column), 32 nodes/block in SMEM.
// ---------------------------------------------------------------------------
template <int F>
__global__ void proj_kv_kernel(const float* __restrict__ X,
                               const float* __restrict__ Wk, const float* __restrict__ bk,
                               const float* __restrict__ Wv, const float* __restrict__ bv,
                               float* __restrict__ K, float* __restrict__ V, int n)
{
    __shared__ float sh[32 * F];
    const int col  = threadIdx.x;           // 0..127
    const int base = blockIdx.x * 32;

    for (int i = threadIdx.x; i < 32 * F; i += 128) {
        int node = base + i / F;
        sh[i] = (node < n) ? X[(size_t)base * F + i] : 0.f;
    }
    __syncthreads();

    const float bkc = bk[col], bvc = bv[col];

    for (int c = 0; c < 4; ++c) {            // 4 chunks of 8 nodes
        float ak[8], av[8];
#pragma unroll
        for (int j = 0; j < 8; ++j) { ak[j] = bkc; av[j] = bvc; }
#pragma unroll 8
        for (int d = 0; d < F; ++d) {
            float wk = Wk[d * HCC + col];
            float wv = Wv[d * HCC + col];
            const float* hr = &sh[(c * 8) * F + d];
#pragma unroll
            for (int j = 0; j < 8; ++j) {
                float xv = hr[j * F];
                ak[j] += xv * wk;
                av[j] += xv * wv;
            }
        }
#pragma unroll
        for (int j = 0; j < 8; ++j) {
            int node = base + c * 8 + j;
            if (node < n) {
                K[(size_t)node * HCC + col] = ak[j];
                V[(size_t)node * HCC + col] = av[j];
            }
        }
    }
}

// ---------------------------------------------------------------------------
// Fused TransformerConv layer (per dst node, one warp):
//   q = hin@Wq+bq (prologue), online-softmax edge loop over CSR segment
//   (gather k/v rows, edge bias from ea@We in registers), then
//   out = msg/z + hin@Ws+bs, hout = relu(out@Wt+bt) via smem exchange.
// Zero global atomics. 8 warps (8 nodes) per block.
// ---------------------------------------------------------------------------
template <int F>
__global__ void tconv_kernel(const float* __restrict__ hin,   // [n,F]
                             const float* __restrict__ kbuf,  // [n,HCC]
                             const float* __restrict__ vbuf,  // [n,HCC]
                             const int*   __restrict__ start,
                             const int*   __restrict__ csr_src,
                             const float* __restrict__ csr_ea,
                             const float* __restrict__ Wq, const float* __restrict__ bq,
                             const float* __restrict__ We,
                             const float* __restrict__ Ws, const float* __restrict__ bs,
                             const float* __restrict__ Wt, const float* __restrict__ bt,
                             float* __restrict__ hout, int n)
{
    __shared__ float sh_o[8][HCC];
    __shared__ float sh_h[8][F];

    const int warp = threadIdx.x >> 5;
    const int lane = threadIdx.x & 31;
    const int node = blockIdx.x * 8 + warp;
    if (node >= n) return;                  // whole warp exits together
    const int off = lane * 4;               // this lane's 4 channels; head = lane>>3

    // stage node features in smem (one 128B broadcast row)
    if (lane < F / 4)
        *(float4*)&sh_h[warp][lane * 4] = *(const float4*)(hin + (size_t)node * F + lane * 4);
    __syncwarp();

    // edge-bias weights for this lane's channels (live in registers)
    const float4 w0 = *(const float4*)(We + 0 * HCC + off);
    const float4 w1 = *(const float4*)(We + 1 * HCC + off);
    const float4 w2 = *(const float4*)(We + 2 * HCC + off);
    const float4 w3 = *(const float4*)(We + 3 * HCC + off);

    // q projection (this lane's 4 channels)
    float4 q4 = *(const float4*)(bq + off);
#pragma unroll
    for (int d = 0; d < F; ++d) {
        float hd = sh_h[warp][d];
        float4 w = *(const float4*)(Wq + d * HCC + off);
        q4.x += hd * w.x; q4.y += hd * w.y; q4.z += hd * w.z; q4.w += hd * w.w;
    }

    const int s0 = start[node], s1 = start[node + 1];

    float m = -3.0e38f, z = 0.f;
    float4 acc = make_float4(0.f, 0.f, 0.f, 0.f);

    for (int pos = s0; pos < s1; ++pos) {
        int src   = __ldg(csr_src + pos);
        float4 ea4 = *(const float4*)(csr_ea + (size_t)pos * 4);
        float4 k4  = *(const float4*)(kbuf + (size_t)src * HCC + off);
        float4 v4  = *(const float4*)(vbuf + (size_t)src * HCC + off);

        float bx = ea4.x * w0.x + ea4.y * w1.x + ea4.z * w2.x + ea4.w * w3.x;
        float by = ea4.x * w0.y + ea4.y * w1.y + ea4.z * w2.y + ea4.w * w3.y;
        float bz = ea4.x * w0.z + ea4.y * w1.z + ea4.z * w2.z + ea4.w * w3.z;
        float bw = ea4.x * w0.w + ea4.y * w1.w + ea4.z * w2.w + ea4.w * w3.w;

        float l = q4.x * (k4.x + bx) + q4.y * (k4.y + by)
                + q4.z * (k4.z + bz) + q4.w * (k4.w + bw);
        // reduce across the 8 lanes of this head
        l += __shfl_xor_sync(0xFFFFFFFFu, l, 1);
        l += __shfl_xor_sync(0xFFFFFFFFu, l, 2);
        l += __shfl_xor_sync(0xFFFFFFFFu, l, 4);
        l *= 0.17677669529663687f;          // 1/sqrt(32)

        // online softmax update (per head, replicated across its 8 lanes)
        float mn = fmaxf(m, l);
        float c  = __expf(m - mn);           // 0 on first edge (m=-3e38)
        float p  = __expf(l - mn);
        z = z * c + p;
        acc.x = acc.x * c + p * (v4.x + bx);
        acc.y = acc.y * c + p * (v4.y + by);
        acc.z = acc.z * c + p * (v4.z + bz);
        acc.w = acc.w * c + p * (v4.w + bw);
        m = mn;
    }

    const float inv = 1.f / (z + 1e-16f);

    // root skip: hin@Ws + bs
    float4 o4 = *(const float4*)(bs + off);
#pragma unroll
    for (int d = 0; d < F; ++d) {
        float hd = sh_h[warp][d];
        float4 w = *(const float4*)(Ws + d * HCC + off);
        o4.x += hd * w.x; o4.y += hd * w.y; o4.z += hd * w.z; o4.w += hd * w.w;
    }
    o4.x += acc.x * inv; o4.y += acc.y * inv;
    o4.z += acc.z * inv; o4.w += acc.w * inv;

    // transform 128 -> 32 with relu, via per-warp smem exchange
    *(float4*)&sh_o[warp][off] = o4;
    __syncwarp();

    float t = bt[lane];
#pragma unroll 4
    for (int c2 = 0; c2 < HCC; ++c2)
        t += sh_o[warp][c2] * Wt[c2 * EMB + lane];
    hout[(size_t)node * EMB + lane] = fmaxf(t, 0.f);
}

// ---------------------------------------------------------------------------
// Dense head (kept from R14 — small share of runtime)
// ---------------------------------------------------------------------------
template <int F, int OUT, bool RELU>
__global__ void linear_kernel(const float* __restrict__ X,
                              const float* __restrict__ W,
                              const float* __restrict__ B,
                              float* __restrict__ Y, int n)
{
    constexpr int SUBS = 128 / OUT;
    constexpr int NPS  = 32 / SUBS;
    constexpr int NCH  = NPS / 8;

    __shared__ float sh[32 * F];

    const int tid  = threadIdx.x;
    const int col  = tid % OUT;
    const int sub  = tid / OUT;
    const int base = blockIdx.x * 32;

    for (int i = tid; i < 32 * F; i += 128) {
        int node = base + i / F;
        sh[i] = (node < n) ? X[(size_t)base * F + i] : 0.f;
    }
    __syncthreads();

    const float bcol = B[col];
    const int nb = sub * NPS;

    for (int c = 0; c < NCH; ++c) {
        float acc[8];
#pragma unroll
        for (int j = 0; j < 8; ++j) acc[j] = bcol;
#pragma unroll 8
        for (int d = 0; d < F; ++d) {
            float w = W[d * OUT + col];
            const float* hrow = &sh[(nb + c * 8) * F + d];
#pragma unroll
            for (int j = 0; j < 8; ++j)
                acc[j] += hrow[j * F] * w;
        }
#pragma unroll
        for (int j = 0; j < 8; ++j) {
            int node = base + nb + c * 8 + j;
            if (node < n) {
                float vv = acc[j];
                if (RELU) vv = fmaxf(vv, 0.f);
                Y[(size_t)node * OUT + col] = vv;
            }
        }
    }
}

__global__ void dense3_kernel(const float* __restrict__ t2,
                              const float* __restrict__ W3,
                              const float* __restrict__ b3,
                              float* __restrict__ out, int n)
{
    int w = (blockIdx.x * blockDim.x + threadIdx.x) >> 5;
    int lane = threadIdx.x & 31;
    if (w >= n) return;
    float s = t2[(size_t)w * 64 + lane]      * W3[lane]
            + t2[(size_t)w * 64 + 32 + lane] * W3[32 + lane];
#pragma unroll
    for (int o = 16; o; o >>= 1) s += __shfl_xor_sync(0xFFFFFFFFu, s, o);
    if (lane == 0) out[w] = 1.f / (1.f + expf(-(s + b3[0])));
}

// ---------------------------------------------------------------------------
extern "C" void kernel_launch(void* const* d_in, const int* in_sizes, int n_in,
                              void* d_out, int out_size)
{
    const float* x   = (const float*)d_in[0];
    const int*   ei  = (const int*)  d_in[1];
    const float* ea  = (const float*)d_in[2];
    const float* Wq0 = (const float*)d_in[3];  const float* bq0 = (const float*)d_in[4];
    const float* Wk0 = (const float*)d_in[5];  const float* bk0 = (const float*)d_in[6];
    const float* Wv0 = (const float*)d_in[7];  const float* bv0 = (const float*)d_in[8];
    const float* We0 = (const float*)d_in[9];
    const float* Ws0 = (const float*)d_in[10]; const float* bs0 = (const float*)d_in[11];
    const float* Wt0 = (const float*)d_in[12]; const float* bt0 = (const float*)d_in[13];
    const float* Wq  = (const float*)d_in[14]; const float* bq  = (const float*)d_in[15];
    const float* Wk  = (const float*)d_in[16]; const float* bk  = (const float*)d_in[17];
    const float* Wv  = (const float*)d_in[18]; const float* bv  = (const float*)d_in[19];
    const float* We  = (const float*)d_in[20];
    const float* Ws  = (const float*)d_in[21]; const float* bs  = (const float*)d_in[22];
    const float* Wt  = (const float*)d_in[23]; const float* bt  = (const float*)d_in[24];
    const float* W1  = (const float*)d_in[25]; const float* b1  = (const float*)d_in[26];
    const float* W2  = (const float*)d_in[27]; const float* b2  = (const float*)d_in[28];
    const float* W3  = (const float*)d_in[29]; const float* b3  = (const float*)d_in[30];

    const int n  = in_sizes[0] / F_IN;
    const int E_ = in_sizes[1] / 2;

    float *kb, *vb, *h, *h2, *t1, *t2, *csr_ea;
    int *deg, *start, *cur, *csr_src, *bsum;
    cudaGetSymbolAddress((void**)&kb, g_k);
    cudaGetSymbolAddress((void**)&vb, g_v);
    cudaGetSymbolAddress((void**)&h,  g_h);
    cudaGetSymbolAddress((void**)&h2, g_h2);
    cudaGetSymbolAddress((void**)&t1, g_t1);
    cudaGetSymbolAddress((void**)&t2, g_t2);
    cudaGetSymbolAddress((void**)&deg, g_deg);
    cudaGetSymbolAddress((void**)&start, g_start);
    cudaGetSymbolAddress((void**)&cur, g_cur);
    cudaGetSymbolAddress((void**)&csr_src, g_csr_src);
    cudaGetSymbolAddress((void**)&csr_ea, g_csr_ea);
    cudaGetSymbolAddress((void**)&bsum, g_bsum);

    const int LBLK = (n + 31) / 32;
    const int TBLK = (n + 7) / 8;
    const int NB   = (n + 255) / 256;
    const int EB   = (E_ + 255) / 256;
    const int SB   = (n + 1023) / 1024;

    float* out = (float*)d_out;

    // ---- CSR build (dst-sorted; reused by all 3 layers) ----
    zero_deg_kernel<<<NB, 256>>>(deg, n);
    hist_kernel<<<EB, 256>>>(ei, deg, E_);
    scan1_kernel<<<SB, 1024>>>(deg, start, bsum, n);
    scan2_kernel<<<1, 32>>>(bsum, SB);
    scan3_kernel<<<NB, 256>>>(start, cur, deg, bsum, n);
    scatter_kernel<<<EB, 256>>>(ei, ea, cur, csr_src, csr_ea, E_);

    // ---- layer 0 (F_IN=16) ----
    proj_kv_kernel<F_IN><<<LBLK, 128>>>(x, Wk0, bk0, Wv0, bv0, kb, vb, n);
    tconv_kernel<F_IN><<<TBLK, 256>>>(x, kb, vb, start, csr_src, csr_ea,
                                      Wq0, bq0, We0, Ws0, bs0, Wt0, bt0, h, n);

    // ---- inner layers (EMB=32) ----
    const float* hin  = h;
    float*       hout = h2;
    for (int i = 0; i < LL; ++i) {
        const float* Wqi = Wq + (size_t)i * EMB * HCC;
        const float* Wki = Wk + (size_t)i * EMB * HCC;
        const float* Wvi = Wv + (size_t)i * EMB * HCC;
        const float* Wsi = Ws + (size_t)i * EMB * HCC;
        const float* Wei = We + (size_t)i * 4 * HCC;
        const float* Wti = Wt + (size_t)i * HCC * EMB;
        const float* bqi = bq + (size_t)i * HCC;
        const float* bki = bk + (size_t)i * HCC;
        const float* bvi = bv + (size_t)i * HCC;
        const float* bsi = bs + (size_t)i * HCC;
        const float* bti = bt + (size_t)i * EMB;

        proj_kv_kernel<EMB><<<LBLK, 128>>>(hin, Wki, bki, Wvi, bvi, kb, vb, n);
        tconv_kernel<EMB><<<TBLK, 256>>>(hin, kb, vb, start, csr_src, csr_ea,
                                         Wqi, bqi, Wei, Wsi, bsi, Wti, bti, hout, n);
        float* tmp = (float*)hin; hin = hout; hout = tmp;
    }
    // after 2 swaps, hin points at the final node features

    // ---- dense head ----
    linear_kernel<EMB, DENSE, true><<<LBLK, 128>>>(hin, W1, b1, t1, n);
    linear_kernel<DENSE, DENSE / 2, true><<<LBLK, 128>>>(t1, W2, b2, t2, n);
    dense3_kernel<<<(n * 32 + 255) / 256, 256>>>(t2, W3, b3, out, n);
}

// round 17
// speedup vs baseline: 2.1326x; 1.0862x over previous
#include <cuda_runtime.h>
#include <cuda_fp16.h>
#include <math.h>

// Problem constants (fixed by the dataset)
#define NN     50000
#define EE     800000
#define F_IN   16
#define EMB    32
#define HH     4
#define HCC    128   // EMB*H
#define LL     2
#define DENSE  128

// ---------------------------------------------------------------------------
// Scratch (static device globals — no runtime allocation allowed)
// ---------------------------------------------------------------------------
// k/v stored fp16, interleaved per node: [k(128 half) | v(128 half)] = 512B/row
__device__ __align__(16) __half g_kv[(size_t)NN * 256];
__device__ __align__(16) float g_h[(size_t)NN * EMB];
__device__ __align__(16) float g_h2[(size_t)NN * EMB];
__device__ __align__(16) float g_t1[(size_t)NN * DENSE];
__device__ __align__(16) float g_t2[(size_t)NN * (DENSE / 2)];
// CSR (built once per launch, reused by all 3 layers)
__device__ int g_deg[NN];
__device__ int g_start[NN + 1];
__device__ int g_cur[NN];
__device__ int g_csr_src[EE];
__device__ __align__(16) float g_csr_ea[(size_t)EE * 4];
__device__ int g_bsum[64];

struct __align__(8) half4 { __half2 lo, hi; };

// ---------------------------------------------------------------------------
// CSR build kernels
// ---------------------------------------------------------------------------
__global__ void zero_deg_kernel(int* __restrict__ deg, int n)
{
    int i = blockIdx.x * blockDim.x + threadIdx.x;
    if (i < n) deg[i] = 0;
}

__global__ void hist_kernel(const int* __restrict__ ei, int* __restrict__ deg, int E_)
{
    int e = blockIdx.x * blockDim.x + threadIdx.x;
    if (e < E_) atomicAdd(&deg[ei[E_ + e]], 1);
}

// per-block inclusive scan (Hillis-Steele), partial results to start[i+1]
__global__ void scan1_kernel(const int* __restrict__ deg, int* __restrict__ start,
                             int* __restrict__ bsum, int n)
{
    __shared__ int sh[1024];
    int i = blockIdx.x * 1024 + threadIdx.x;
    int v = (i < n) ? deg[i] : 0;
    sh[threadIdx.x] = v;
    __syncthreads();
    for (int off = 1; off < 1024; off <<= 1) {
        int t = (threadIdx.x >= off) ? sh[threadIdx.x - off] : 0;
        __syncthreads();
        sh[threadIdx.x] += t;
        __syncthreads();
    }
    if (i < n) start[i + 1] = sh[threadIdx.x];
    if (threadIdx.x == 1023) bsum[blockIdx.x] = sh[1023];
}

// parallel exclusive scan over <=64 block sums
__global__ void scan2_kernel(int* __restrict__ bsum, int nb)
{
    __shared__ int sh[64];
    int t = threadIdx.x;
    int v = (t < nb) ? bsum[t] : 0;
    sh[t] = v;
    __syncthreads();
    for (int off = 1; off < 64; off <<= 1) {
        int u = (t >= off) ? sh[t - off] : 0;
        __syncthreads();
        sh[t] += u;
        __syncthreads();
    }
    if (t < nb) bsum[t] = sh[t] - v;   // exclusive
}

__global__ void scan3_kernel(int* __restrict__ start, int* __restrict__ cur,
                             const int* __restrict__ deg, const int* __restrict__ bsum, int n)
{
    int i = blockIdx.x * blockDim.x + threadIdx.x;
    if (i >= n) return;
    int incl = start[i + 1] + bsum[i >> 10];
    start[i + 1] = incl;
    cur[i] = incl - deg[i];
    if (i == 0) start[0] = 0;
}

__global__ void scatter_kernel(const int* __restrict__ ei, const float* __restrict__ ea,
                               int* __restrict__ cur, int* __restrict__ csr_src,
                               float* __restrict__ csr_ea, int E_)
{
    int e = blockIdx.x * blockDim.x + threadIdx.x;
    if (e >= E_) return;
    int dst = ei[E_ + e];
    int pos = atomicAdd(&cur[dst], 1);
    csr_src[pos] = ei[e];
    *(float4*)(csr_ea + (size_t)pos * 4) = *(const float4*)(ea + (size_t)e * 4);
}

// ---------------------------------------------------------------------------
// Fused k/v projection -> fp16 interleaved buffer.
// 128 threads/block (one per output column), 32 nodes/block in SMEM.
// ---------------------------------------------------------------------------
template <int F>
__global__ void proj_kv_kernel(const float* __restrict__ X,
                               const float* __restrict__ Wk, const float* __restrict__ bk,
                               const float* __restrict__ Wv, const float* __restrict__ bv,
                               __half* __restrict__ kv, int n)
{
    __shared__ float sh[32 * F];
    const int col  = threadIdx.x;           // 0..127
    const int base = blockIdx.x * 32;

    for (int i = threadIdx.x; i < 32 * F; i += 128) {
        int node = base + i / F;
        sh[i] = (node < n) ? X[(size_t)base * F + i] : 0.f;
    }
    __syncthreads();

    const float bkc = bk[col], bvc = bv[col];

    for (int c = 0; c < 4; ++c) {            // 4 chunks of 8 nodes
        float ak[8], av[8];
#pragma unroll
        for (int j = 0; j < 8; ++j) { ak[j] = bkc; av[j] = bvc; }
#pragma unroll 8
        for (int d = 0; d < F; ++d) {
            float wk = Wk[d * HCC + col];
            float wv = Wv[d * HCC + col];
            const float* hr = &sh[(c * 8) * F + d];
#pragma unroll
            for (int j = 0; j < 8; ++j) {
                float xv = hr[j * F];
                ak[j] += xv * wk;
                av[j] += xv * wv;
            }
        }
#pragma unroll
        for (int j = 0; j < 8; ++j) {
            int node = base + c * 8 + j;
            if (node < n) {
                kv[(size_t)node * 256 + col]       = __float2half_rn(ak[j]);
                kv[(size_t)node * 256 + 128 + col] = __float2half_rn(av[j]);
            }
        }
    }
}

// ---------------------------------------------------------------------------
// Fused TransformerConv layer: one warp per dst node, 8 warps/block.
// q/skip projections in-warp (float4 weight loads), edge loop over CSR with
// online softmax (2-edge unroll, fp16 k/v gathers), transform via SMEM-staged
// Wt. Zero global atomics.
// ---------------------------------------------------------------------------
template <int F>
__global__ void tconv_kernel(const float* __restrict__ hin,   // [n,F]
                             const __half* __restrict__ kv,   // [n,256]
                             const int*   __restrict__ start,
                             const int*   __restrict__ csr_src,
                             const float* __restrict__ csr_ea,
                             const float* __restrict__ Wq, const float* __restrict__ bq,
                             const float* __restrict__ We,
                             const float* __restrict__ Ws, const float* __restrict__ bs,
                             const float* __restrict__ Wt, const float* __restrict__ bt,
                             float* __restrict__ hout, int n)
{
    __shared__ float sh_wt[HCC * EMB];   // 16 KB, reused by all 8 nodes
    __shared__ float sh_o[8][HCC];
    __shared__ float sh_h[8][F];

    // cooperative Wt stage
    for (int i = threadIdx.x; i < HCC * EMB / 4; i += blockDim.x)
        ((float4*)sh_wt)[i] = ((const float4*)Wt)[i];

    const int warp = threadIdx.x >> 5;
    const int lane = threadIdx.x & 31;
    const int node = blockIdx.x * 8 + warp;
    const int off  = lane * 4;              // this lane's 4 channels; head = lane>>3

    if (node < n && lane < F / 4)
        *(float4*)&sh_h[warp][lane * 4] = *(const float4*)(hin + (size_t)node * F + lane * 4);

    __syncthreads();                        // sh_wt + sh_h ready

    if (node < n) {
        // edge-bias weights for this lane's channels (registers)
        const float4 w0 = *(const float4*)(We + 0 * HCC + off);
        const float4 w1 = *(const float4*)(We + 1 * HCC + off);
        const float4 w2 = *(const float4*)(We + 2 * HCC + off);
        const float4 w3 = *(const float4*)(We + 3 * HCC + off);

        // q projection (this lane's 4 channels)
        float4 q4 = *(const float4*)(bq + off);
#pragma unroll
        for (int d = 0; d < F; ++d) {
            float hd = sh_h[warp][d];
            float4 w = *(const float4*)(Wq + d * HCC + off);
            q4.x += hd * w.x; q4.y += hd * w.y; q4.z += hd * w.z; q4.w += hd * w.w;
        }

        const int s0 = start[node], s1 = start[node + 1];

        float m = -3.0e38f, z = 0.f;
        float4 acc = make_float4(0.f, 0.f, 0.f, 0.f);

        auto step = [&](int src, const float4& ea4) {
            const __half* row = kv + (size_t)src * 256;
            half4 kh = *(const half4*)(row + off);
            half4 vh = *(const half4*)(row + 128 + off);
            float2 k01 = __half22float2(kh.lo), k23 = __half22float2(kh.hi);
            float2 v01 = __half22float2(vh.lo), v23 = __half22float2(vh.hi);

            float bx = ea4.x * w0.x + ea4.y * w1.x + ea4.z * w2.x + ea4.w * w3.x;
            float by = ea4.x * w0.y + ea4.y * w1.y + ea4.z * w2.y + ea4.w * w3.y;
            float bz = ea4.x * w0.z + ea4.y * w1.z + ea4.z * w2.z + ea4.w * w3.z;
            float bw = ea4.x * w0.w + ea4.y * w1.w + ea4.z * w2.w + ea4.w * w3.w;

            float l = q4.x * (k01.x + bx) + q4.y * (k01.y + by)
                    + q4.z * (k23.x + bz) + q4.w * (k23.y + bw);
            l += __shfl_xor_sync(0xFFFFFFFFu, l, 1);
            l += __shfl_xor_sync(0xFFFFFFFFu, l, 2);
            l += __shfl_xor_sync(0xFFFFFFFFu, l, 4);
            l *= 0.17677669529663687f;      // 1/sqrt(32)

            float mn = fmaxf(m, l);
            float c  = __expf(m - mn);       // 0 on first edge
            float p  = __expf(l - mn);
            z = z * c + p;
            acc.x = acc.x * c + p * (v01.x + bx);
            acc.y = acc.y * c + p * (v01.y + by);
            acc.z = acc.z * c + p * (v23.x + bz);
            acc.w = acc.w * c + p * (v23.y + bw);
            m = mn;
        };

        int pos = s0;
        for (; pos + 2 <= s1; pos += 2) {
            // batch both edges' indices/attrs first -> MLP
            int srcA = __ldg(csr_src + pos);
            int srcB = __ldg(csr_src + pos + 1);
            float4 eaA = *(const float4*)(csr_ea + (size_t)pos * 4);
            float4 eaB = *(const float4*)(csr_ea + (size_t)(pos + 1) * 4);
            step(srcA, eaA);
            step(srcB, eaB);
        }
        if (pos < s1) {
            int srcA = __ldg(csr_src + pos);
            float4 eaA = *(const float4*)(csr_ea + (size_t)pos * 4);
            step(srcA, eaA);
        }

        const float inv = 1.f / (z + 1e-16f);

        // root skip: hin@Ws + bs
        float4 o4 = *(const float4*)(bs + off);
#pragma unroll
        for (int d = 0; d < F; ++d) {
            float hd = sh_h[warp][d];
            float4 w = *(const float4*)(Ws + d * HCC + off);
            o4.x += hd * w.x; o4.y += hd * w.y; o4.z += hd * w.z; o4.w += hd * w.w;
        }
        o4.x += acc.x * inv; o4.y += acc.y * inv;
        o4.z += acc.z * inv; o4.w += acc.w * inv;

        // transform 128 -> 32 with relu, via per-warp smem exchange + smem Wt
        *(float4*)&sh_o[warp][off] = o4;
        __syncwarp();

        float t = bt[lane];
#pragma unroll 8
        for (int c2 = 0; c2 < HCC; ++c2)
            t += sh_o[warp][c2] * sh_wt[c2 * EMB + lane];
        hout[(size_t)node * EMB + lane] = fmaxf(t, 0.f);
    }
}

// ---------------------------------------------------------------------------
// Dense head
// ---------------------------------------------------------------------------
template <int F, int OUT, bool RELU>
__global__ void linear_kernel(const float* __restrict__ X,
                              const float* __restrict__ W,
                              const float* __restrict__ B,
                              float* __restrict__ Y, int n)
{
    constexpr int SUBS = 128 / OUT;
    constexpr int NPS  = 32 / SUBS;
    constexpr int NCH  = NPS / 8;

    __shared__ float sh[32 * F];

    const int tid  = threadIdx.x;
    const int col  = tid % OUT;
    const int sub  = tid / OUT;
    const int base = blockIdx.x * 32;

    for (int i = tid; i < 32 * F; i += 128) {
        int node = base + i / F;
        sh[i] = (node < n) ? X[(size_t)base * F + i] : 0.f;
    }
    __syncthreads();

    const float bcol = B[col];
    const int nb = sub * NPS;

    for (int c = 0; c < NCH; ++c) {
        float acc[8];
#pragma unroll
        for (int j = 0; j < 8; ++j) acc[j] = bcol;
#pragma unroll 8
        for (int d = 0; d < F; ++d) {
            float w = W[d * OUT + col];
            const float* hrow = &sh[(nb + c * 8) * F + d];
#pragma unroll
            for (int j = 0; j < 8; ++j)
                acc[j] += hrow[j * F] * w;
        }
#pragma unroll
        for (int j = 0; j < 8; ++j) {
            int node = base + nb + c * 8 + j;
            if (node < n) {
                float vv = acc[j];
                if (RELU) vv = fmaxf(vv, 0.f);
                Y[(size_t)node * OUT + col] = vv;
            }
        }
    }
}

__global__ void dense3_kernel(const float* __restrict__ t2,
                              const float* __restrict__ W3,
                              const float* __restrict__ b3,
                              float* __restrict__ out, int n)
{
    int w = (blockIdx.x * blockDim.x + threadIdx.x) >> 5;
    int lane = threadIdx.x & 31;
    if (w >= n) return;
    float s = t2[(size_t)w * 64 + lane]      * W3[lane]
            + t2[(size_t)w * 64 + 32 + lane] * W3[32 + lane];
#pragma unroll
    for (int o = 16; o; o >>= 1) s += __shfl_xor_sync(0xFFFFFFFFu, s, o);
    if (lane == 0) out[w] = 1.f / (1.f + expf(-(s + b3[0])));
}

// ---------------------------------------------------------------------------
extern "C" void kernel_launch(void* const* d_in, const int* in_sizes, int n_in,
                              void* d_out, int out_size)
{
    const float* x   = (const float*)d_in[0];
    const int*   ei  = (const int*)  d_in[1];
    const float* ea  = (const float*)d_in[2];
    const float* Wq0 = (const float*)d_in[3];  const float* bq0 = (const float*)d_in[4];
    const float* Wk0 = (const float*)d_in[5];  const float* bk0 = (const float*)d_in[6];
    const float* Wv0 = (const float*)d_in[7];  const float* bv0 = (const float*)d_in[8];
    const float* We0 = (const float*)d_in[9];
    const float* Ws0 = (const float*)d_in[10]; const float* bs0 = (const float*)d_in[11];
    const float* Wt0 = (const float*)d_in[12]; const float* bt0 = (const float*)d_in[13];
    const float* Wq  = (const float*)d_in[14]; const float* bq  = (const float*)d_in[15];
    const float* Wk  = (const float*)d_in[16]; const float* bk  = (const float*)d_in[17];
    const float* Wv  = (const float*)d_in[18]; const float* bv  = (const float*)d_in[19];
    const float* We  = (const float*)d_in[20];
    const float* Ws  = (const float*)d_in[21]; const float* bs  = (const float*)d_in[22];
    const float* Wt  = (const float*)d_in[23]; const float* bt  = (const float*)d_in[24];
    const float* W1  = (const float*)d_in[25]; const float* b1  = (const float*)d_in[26];
    const float* W2  = (const float*)d_in[27]; const float* b2  = (const float*)d_in[28];
    const float* W3  = (const float*)d_in[29]; const float* b3  = (const float*)d_in[30];

    const int n  = in_sizes[0] / F_IN;
    const int E_ = in_sizes[1] / 2;

    __half* kvb;
    float *h, *h2, *t1, *t2, *csr_ea;
    int *deg, *start, *cur, *csr_src, *bsum;
    cudaGetSymbolAddress((void**)&kvb, g_kv);
    cudaGetSymbolAddress((void**)&h,  g_h);
    cudaGetSymbolAddress((void**)&h2, g_h2);
    cudaGetSymbolAddress((void**)&t1, g_t1);
    cudaGetSymbolAddress((void**)&t2, g_t2);
    cudaGetSymbolAddress((void**)&deg, g_deg);
    cudaGetSymbolAddress((void**)&start, g_start);
    cudaGetSymbolAddress((void**)&cur, g_cur);
    cudaGetSymbolAddress((void**)&csr_src, g_csr_src);
    cudaGetSymbolAddress((void**)&csr_ea, g_csr_ea);
    cudaGetSymbolAddress((void**)&bsum, g_bsum);

    const int LBLK = (n + 31) / 32;
    const int TBLK = (n + 7) / 8;
    const int NB   = (n + 255) / 256;
    const int EB   = (E_ + 255) / 256;
    const int SB   = (n + 1023) / 1024;

    float* out = (float*)d_out;

    // ---- CSR build (dst-sorted; reused by all 3 layers) ----
    zero_deg_kernel<<<NB, 256>>>(deg, n);
    hist_kernel<<<EB, 256>>>(ei, deg, E_);
    scan1_kernel<<<SB, 1024>>>(deg, start, bsum, n);
    scan2_kernel<<<1, 64>>>(bsum, SB);
    scan3_kernel<<<NB, 256>>>(start, cur, deg, bsum, n);
    scatter_kernel<<<EB, 256>>>(ei, ea, cur, csr_src, csr_ea, E_);

    // ---- layer 0 (F_IN=16) ----
    proj_kv_kernel<F_IN><<<LBLK, 128>>>(x, Wk0, bk0, Wv0, bv0, kvb, n);
    tconv_kernel<F_IN><<<TBLK, 256>>>(x, kvb, start, csr_src, csr_ea,
                                      Wq0, bq0, We0, Ws0, bs0, Wt0, bt0, h, n);

    // ---- inner layers (EMB=32) ----
    const float* hin  = h;
    float*       hout = h2;
    for (int i = 0; i < LL; ++i) {
        const float* Wqi = Wq + (size_t)i * EMB * HCC;
        const float* Wki = Wk + (size_t)i * EMB * HCC;
        const float* Wvi = Wv + (size_t)i * EMB * HCC;
        const float* Wsi = Ws + (size_t)i * EMB * HCC;
        const float* Wei = We + (size_t)i * 4 * HCC;
        const float* Wti = Wt + (size_t)i * HCC * EMB;
        const float* bqi = bq + (size_t)i * HCC;
        const float* bki = bk + (size_t)i * HCC;
        const float* bvi = bv + (size_t)i * HCC;
        const float* bsi = bs + (size_t)i * HCC;
        const float* bti = bt + (size_t)i * EMB;

        proj_kv_kernel<EMB><<<LBLK, 128>>>(hin, Wki, bki, Wvi, bvi, kvb, n);
        tconv_kernel<EMB><<<TBLK, 256>>>(hin, kvb, start, csr_src, csr_ea,
                                         Wqi, bqi, Wei, Wsi, bsi, Wti, bti, hout, n);
        float* tmp = (float*)hin; hin = hout; hout = tmp;
    }

    // ---- dense head ----
    linear_kernel<EMB, DENSE, true><<<LBLK, 128>>>(hin, W1, b1, t1, n);
    linear_kernel<DENSE, DENSE / 2, true><<<LBLK, 128>>>(t1, W2, b2, t2, n);
    dense3_kernel<<<(n * 32 + 255) / 256, 256>>>(t2, W3, b3, out, n);
}